// round 13
// baseline (speedup 1.0000x reference)
#include <cuda_runtime.h>

// Problem constants (fixed by the reference)
#define BB      16      // batch
#define HH      32      // heads
#define DD      128     // head dim
#define NBLK    1024    // cache blocks
#define BSZ     16      // tokens per block
#define MBLK    128     // max blocks per seq
#define SEQ     (MBLK * BSZ)   // 2048
#define HIDDEN  (HH * DD)      // 4096

#define NSPLIT  8
#define CHUNK   (SEQ / NSPLIT)     // 256 tokens per split
#define NWARP   8
#define TPW     (CHUNK / NWARP)    // 32 tokens per warp

// Scratch (device globals — no allocation allowed)
__device__ float g_q[BB * HIDDEN];                    // normalized q
__device__ float g_acc[BB * HH * NSPLIT * DD];        // split partial accumulators
__device__ float g_ml[BB * HH * NSPLIT * 2];          // split (max, sumexp)

// ---------------------------------------------------------------------------
// Kernel 1: RMSNorm -> q scratch.  One CTA per batch row (4096 f32).
// ---------------------------------------------------------------------------
__global__ void rms_kernel(const float* __restrict__ x,
                           const float* __restrict__ w) {
    const int b = blockIdx.x;
    const float4* row = (const float4*)(x + b * HIDDEN);   // 1024 float4
    const int tid  = threadIdx.x;                           // 256 threads
    const int lane = tid & 31;
    const int warp = tid >> 5;

    float4 vals[4];
    float ss = 0.f;
#pragma unroll
    for (int i = 0; i < 4; i++) {
        float4 v = row[tid + i * 256];
        vals[i] = v;
        ss += v.x * v.x + v.y * v.y + v.z * v.z + v.w * v.w;
    }
#pragma unroll
    for (int o = 16; o; o >>= 1) ss += __shfl_xor_sync(0xffffffffu, ss, o);

    __shared__ float sred[8];
    __shared__ float s_inv;
    if (lane == 0) sred[warp] = ss;
    __syncthreads();
    if (tid == 0) {
        float t = 0.f;
#pragma unroll
        for (int i = 0; i < 8; i++) t += sred[i];
        s_inv = rsqrtf(t * (1.0f / HIDDEN) + 1e-6f);
    }
    __syncthreads();
    const float inv = s_inv;

    const float4* w4 = (const float4*)w;
    float4* q4 = (float4*)(g_q + b * HIDDEN);
#pragma unroll
    for (int i = 0; i < 4; i++) {
        int idx = tid + i * 256;
        float4 v = vals[i];
        float4 ww = w4[idx];
        float4 o;
        o.x = v.x * inv * ww.x;
        o.y = v.y * inv * ww.y;
        o.z = v.z * inv * ww.z;
        o.w = v.w * inv * ww.w;
        q4[idx] = o;
    }
}

// ---------------------------------------------------------------------------
// Kernel 2: split paged attention (flash-decode partial).
// grid = (NSPLIT, H, B), block = 256 (8 warps). Warp-per-token dot products.
// ---------------------------------------------------------------------------
__global__ void __launch_bounds__(256, 8)
attn_partial(const float* __restrict__ kc,
             const float* __restrict__ vc,
             const int*   __restrict__ bt,
             const int*   __restrict__ cl) {
    const int split = blockIdx.x;
    const int h     = blockIdx.y;
    const int b     = blockIdx.z;

    const int L     = cl[b];
    const int start = split * CHUNK;
    const int pidx  = (b * HH + h) * NSPLIT + split;

    if (start >= L) {
        if (threadIdx.x == 0) {
            g_ml[2 * pidx]     = -1e30f;
            g_ml[2 * pidx + 1] = 0.f;
        }
        return;
    }
    const int end = min(start + CHUNK, L);

    __shared__ int   bt_s[CHUNK / BSZ];          // 16 block ids for this chunk
    __shared__ float s_m[NWARP], s_l[NWARP];
    __shared__ float s_acc[NWARP][DD];

    if (threadIdx.x < CHUNK / BSZ)
        bt_s[threadIdx.x] = bt[b * MBLK + (start >> 4) + threadIdx.x];

    const int warp = threadIdx.x >> 5;
    const int lane = threadIdx.x & 31;

    const float4 q4 = ((const float4*)(g_q + b * HIDDEN + h * DD))[lane];
    __syncthreads();

    const float scale = 0.08838834764831845f;   // 1/sqrt(128)

    float  m = -1e30f, l = 0.f;
    float4 acc = make_float4(0.f, 0.f, 0.f, 0.f);

    const int t0 = start + warp * TPW;
    const int t1 = min(t0 + TPW, end);

    int t = t0;
    // 2-token unrolled main loop: issue both K/V pairs before updating state.
    for (; t + 1 < t1; t += 2) {
        int lc0 = t - start, lc1 = lc0 + 1;
        size_t r0 = ((size_t)bt_s[lc0 >> 4] * BSZ + (t & (BSZ - 1))) * HH + h;
        size_t r1 = ((size_t)bt_s[lc1 >> 4] * BSZ + ((t + 1) & (BSZ - 1))) * HH + h;
        float4 k0 = __ldg((const float4*)(kc + r0 * DD) + lane);
        float4 k1 = __ldg((const float4*)(kc + r1 * DD) + lane);
        float4 v0 = __ldg((const float4*)(vc + r0 * DD) + lane);
        float4 v1 = __ldg((const float4*)(vc + r1 * DD) + lane);

        float s0 = k0.x * q4.x + k0.y * q4.y + k0.z * q4.z + k0.w * q4.w;
        float s1 = k1.x * q4.x + k1.y * q4.y + k1.z * q4.z + k1.w * q4.w;
#pragma unroll
        for (int o = 16; o; o >>= 1) {
            s0 += __shfl_xor_sync(0xffffffffu, s0, o);
            s1 += __shfl_xor_sync(0xffffffffu, s1, o);
        }
        s0 *= scale;
        s1 *= scale;

        float mn    = fmaxf(m, fmaxf(s0, s1));
        float alpha = __expf(m - mn);
        float p0    = __expf(s0 - mn);
        float p1    = __expf(s1 - mn);
        l = l * alpha + p0 + p1;
        acc.x = acc.x * alpha + p0 * v0.x + p1 * v1.x;
        acc.y = acc.y * alpha + p0 * v0.y + p1 * v1.y;
        acc.z = acc.z * alpha + p0 * v0.z + p1 * v1.z;
        acc.w = acc.w * alpha + p0 * v0.w + p1 * v1.w;
        m = mn;
    }
    // tail (0 or 1 token)
    for (; t < t1; ++t) {
        int lc = t - start;
        size_t r = ((size_t)bt_s[lc >> 4] * BSZ + (t & (BSZ - 1))) * HH + h;
        float4 k = __ldg((const float4*)(kc + r * DD) + lane);
        float4 v = __ldg((const float4*)(vc + r * DD) + lane);
        float s = k.x * q4.x + k.y * q4.y + k.z * q4.z + k.w * q4.w;
#pragma unroll
        for (int o = 16; o; o >>= 1) s += __shfl_xor_sync(0xffffffffu, s, o);
        s *= scale;
        float mn    = fmaxf(m, s);
        float alpha = __expf(m - mn);
        float p     = __expf(s - mn);
        l = l * alpha + p;
        acc.x = acc.x * alpha + p * v.x;
        acc.y = acc.y * alpha + p * v.y;
        acc.z = acc.z * alpha + p * v.z;
        acc.w = acc.w * alpha + p * v.w;
        m = mn;
    }

    // Combine the 8 warp partials.
    ((float4*)s_acc[warp])[lane] = acc;
    if (lane == 0) { s_m[warp] = m; s_l[warp] = l; }
    __syncthreads();

    if (threadIdx.x < DD) {
        const int d = threadIdx.x;
        float M = -1e30f;
#pragma unroll
        for (int w = 0; w < NWARP; w++) M = fmaxf(M, s_m[w]);
        float lt = 0.f, a = 0.f;
#pragma unroll
        for (int w = 0; w < NWARP; w++) {
            float e = __expf(s_m[w] - M);
            lt += s_l[w] * e;
            a  += s_acc[w][d] * e;
        }
        g_acc[(size_t)pidx * DD + d] = a;
        if (d == 0) {
            g_ml[2 * pidx]     = M;
            g_ml[2 * pidx + 1] = lt;
        }
    }
}

// ---------------------------------------------------------------------------
// Kernel 3: reduce splits + residual add. grid = B*H, block = 128.
// ---------------------------------------------------------------------------
__global__ void attn_reduce(const float* __restrict__ hidden,
                            float* __restrict__ out) {
    const int bh = blockIdx.x;           // b*H + h
    const int d  = threadIdx.x;          // 0..127

    float M = -1e30f;
#pragma unroll
    for (int s = 0; s < NSPLIT; s++)
        M = fmaxf(M, g_ml[2 * (bh * NSPLIT + s)]);

    float lt = 0.f, a = 0.f;
#pragma unroll
    for (int s = 0; s < NSPLIT; s++) {
        int p  = bh * NSPLIT + s;
        float e = __expf(g_ml[2 * p] - M);      // 0 for empty splits
        lt += g_ml[2 * p + 1] * e;
        a  += g_acc[(size_t)p * DD + d] * e;
    }

    const int idx = bh * DD + d;                // b*HIDDEN + h*DD + d
    out[idx] = hidden[idx] + a / lt;
}

// ---------------------------------------------------------------------------
extern "C" void kernel_launch(void* const* d_in, const int* in_sizes, int n_in,
                              void* d_out, int out_size) {
    const float* hidden = (const float*)d_in[0];   // [B, HIDDEN]
    const float* kc     = (const float*)d_in[1];   // [NB, BS, H, D]
    const float* vc     = (const float*)d_in[2];   // [NB, BS, H, D]
    const int*   bt     = (const int*)  d_in[3];   // [B, MB]
    const int*   cl     = (const int*)  d_in[4];   // [B]
    const float* w      = (const float*)d_in[5];   // [HIDDEN]
    float* out = (float*)d_out;

    rms_kernel<<<BB, 256>>>(hidden, w);

    dim3 grid(NSPLIT, HH, BB);
    attn_partial<<<grid, 256>>>(kc, vc, bt, cl);

    attn_reduce<<<BB * HH, DD>>>(hidden, out);
}

// round 14
// speedup vs baseline: 1.0004x; 1.0004x over previous
#include <cuda_runtime.h>

// Problem constants (fixed by the reference)
#define BB      16      // batch
#define HH      32      // heads
#define DD      128     // head dim
#define NBLK    1024    // cache blocks
#define BSZ     16      // tokens per block
#define MBLK    128     // max blocks per seq
#define SEQ     (MBLK * BSZ)   // 2048
#define HIDDEN  (HH * DD)      // 4096

#define NSPLIT  8
#define CHUNK   (SEQ / NSPLIT)     // 256 tokens per split
#define NWARP   8
#define TPW     (CHUNK / NWARP)    // 32 tokens per warp

// Scratch (device globals — no allocation allowed)
__device__ float g_q[BB * HIDDEN];                    // normalized q
__device__ float g_acc[BB * HH * NSPLIT * DD];        // split partial accumulators
__device__ float g_ml[BB * HH * NSPLIT * 2];          // split (max, sumexp)

// ---------------------------------------------------------------------------
// Kernel 1: RMSNorm -> q scratch.  One CTA per batch row (4096 f32).
// ---------------------------------------------------------------------------
__global__ void rms_kernel(const float* __restrict__ x,
                           const float* __restrict__ w) {
    const int b = blockIdx.x;
    const float4* row = (const float4*)(x + b * HIDDEN);   // 1024 float4
    const int tid  = threadIdx.x;                           // 256 threads
    const int lane = tid & 31;
    const int warp = tid >> 5;

    float4 vals[4];
    float ss = 0.f;
#pragma unroll
    for (int i = 0; i < 4; i++) {
        float4 v = row[tid + i * 256];
        vals[i] = v;
        ss += v.x * v.x + v.y * v.y + v.z * v.z + v.w * v.w;
    }
#pragma unroll
    for (int o = 16; o; o >>= 1) ss += __shfl_xor_sync(0xffffffffu, ss, o);

    __shared__ float sred[8];
    __shared__ float s_inv;
    if (lane == 0) sred[warp] = ss;
    __syncthreads();
    if (tid == 0) {
        float t = 0.f;
#pragma unroll
        for (int i = 0; i < 8; i++) t += sred[i];
        s_inv = rsqrtf(t * (1.0f / HIDDEN) + 1e-6f);
    }
    __syncthreads();
    const float inv = s_inv;

    const float4* w4 = (const float4*)w;
    float4* q4 = (float4*)(g_q + b * HIDDEN);
#pragma unroll
    for (int i = 0; i < 4; i++) {
        int idx = tid + i * 256;
        float4 v = vals[i];
        float4 ww = w4[idx];
        float4 o;
        o.x = v.x * inv * ww.x;
        o.y = v.y * inv * ww.y;
        o.z = v.z * inv * ww.z;
        o.w = v.w * inv * ww.w;
        q4[idx] = o;
    }
}

// ---------------------------------------------------------------------------
// Kernel 2: split paged attention (flash-decode partial).
// grid = (NSPLIT, H, B), block = 256 (8 warps). Warp-per-token dot products.
// ---------------------------------------------------------------------------
__global__ void __launch_bounds__(256, 8)
attn_partial(const float* __restrict__ kc,
             const float* __restrict__ vc,
             const int*   __restrict__ bt,
             const int*   __restrict__ cl) {
    const int split = blockIdx.x;
    const int h     = blockIdx.y;
    const int b     = blockIdx.z;

    const int L     = cl[b];
    const int start = split * CHUNK;
    const int pidx  = (b * HH + h) * NSPLIT + split;

    if (start >= L) {
        if (threadIdx.x == 0) {
            g_ml[2 * pidx]     = -1e30f;
            g_ml[2 * pidx + 1] = 0.f;
        }
        return;
    }
    const int end = min(start + CHUNK, L);

    __shared__ int   bt_s[CHUNK / BSZ];          // 16 block ids for this chunk
    __shared__ float s_m[NWARP], s_l[NWARP];
    __shared__ float s_acc[NWARP][DD];

    if (threadIdx.x < CHUNK / BSZ)
        bt_s[threadIdx.x] = bt[b * MBLK + (start >> 4) + threadIdx.x];

    const int warp = threadIdx.x >> 5;
    const int lane = threadIdx.x & 31;

    const float4 q4 = ((const float4*)(g_q + b * HIDDEN + h * DD))[lane];
    __syncthreads();

    const float scale = 0.08838834764831845f;   // 1/sqrt(128)

    float  m = -1e30f, l = 0.f;
    float4 acc = make_float4(0.f, 0.f, 0.f, 0.f);

    const int t0 = start + warp * TPW;
    const int t1 = min(t0 + TPW, end);

    int t = t0;
    // 2-token unrolled main loop: issue both K/V pairs before updating state.
    for (; t + 1 < t1; t += 2) {
        int lc0 = t - start, lc1 = lc0 + 1;
        size_t r0 = ((size_t)bt_s[lc0 >> 4] * BSZ + (t & (BSZ - 1))) * HH + h;
        size_t r1 = ((size_t)bt_s[lc1 >> 4] * BSZ + ((t + 1) & (BSZ - 1))) * HH + h;
        float4 k0 = __ldg((const float4*)(kc + r0 * DD) + lane);
        float4 k1 = __ldg((const float4*)(kc + r1 * DD) + lane);
        float4 v0 = __ldg((const float4*)(vc + r0 * DD) + lane);
        float4 v1 = __ldg((const float4*)(vc + r1 * DD) + lane);

        float s0 = k0.x * q4.x + k0.y * q4.y + k0.z * q4.z + k0.w * q4.w;
        float s1 = k1.x * q4.x + k1.y * q4.y + k1.z * q4.z + k1.w * q4.w;
#pragma unroll
        for (int o = 16; o; o >>= 1) {
            s0 += __shfl_xor_sync(0xffffffffu, s0, o);
            s1 += __shfl_xor_sync(0xffffffffu, s1, o);
        }
        s0 *= scale;
        s1 *= scale;

        float mn    = fmaxf(m, fmaxf(s0, s1));
        float alpha = __expf(m - mn);
        float p0    = __expf(s0 - mn);
        float p1    = __expf(s1 - mn);
        l = l * alpha + p0 + p1;
        acc.x = acc.x * alpha + p0 * v0.x + p1 * v1.x;
        acc.y = acc.y * alpha + p0 * v0.y + p1 * v1.y;
        acc.z = acc.z * alpha + p0 * v0.z + p1 * v1.z;
        acc.w = acc.w * alpha + p0 * v0.w + p1 * v1.w;
        m = mn;
    }
    // tail (0 or 1 token)
    for (; t < t1; ++t) {
        int lc = t - start;
        size_t r = ((size_t)bt_s[lc >> 4] * BSZ + (t & (BSZ - 1))) * HH + h;
        float4 k = __ldg((const float4*)(kc + r * DD) + lane);
        float4 v = __ldg((const float4*)(vc + r * DD) + lane);
        float s = k.x * q4.x + k.y * q4.y + k.z * q4.z + k.w * q4.w;
#pragma unroll
        for (int o = 16; o; o >>= 1) s += __shfl_xor_sync(0xffffffffu, s, o);
        s *= scale;
        float mn    = fmaxf(m, s);
        float alpha = __expf(m - mn);
        float p     = __expf(s - mn);
        l = l * alpha + p;
        acc.x = acc.x * alpha + p * v.x;
        acc.y = acc.y * alpha + p * v.y;
        acc.z = acc.z * alpha + p * v.z;
        acc.w = acc.w * alpha + p * v.w;
        m = mn;
    }

    // Combine the 8 warp partials.
    ((float4*)s_acc[warp])[lane] = acc;
    if (lane == 0) { s_m[warp] = m; s_l[warp] = l; }
    __syncthreads();

    if (threadIdx.x < DD) {
        const int d = threadIdx.x;
        float M = -1e30f;
#pragma unroll
        for (int w = 0; w < NWARP; w++) M = fmaxf(M, s_m[w]);
        float lt = 0.f, a = 0.f;
#pragma unroll
        for (int w = 0; w < NWARP; w++) {
            float e = __expf(s_m[w] - M);
            lt += s_l[w] * e;
            a  += s_acc[w][d] * e;
        }
        g_acc[(size_t)pidx * DD + d] = a;
        if (d == 0) {
            g_ml[2 * pidx]     = M;
            g_ml[2 * pidx + 1] = lt;
        }
    }
}

// ---------------------------------------------------------------------------
// Kernel 3: reduce splits + residual add. grid = B*H, block = 128.
// ---------------------------------------------------------------------------
__global__ void attn_reduce(const float* __restrict__ hidden,
                            float* __restrict__ out) {
    const int bh = blockIdx.x;           // b*H + h
    const int d  = threadIdx.x;          // 0..127

    float M = -1e30f;
#pragma unroll
    for (int s = 0; s < NSPLIT; s++)
        M = fmaxf(M, g_ml[2 * (bh * NSPLIT + s)]);

    float lt = 0.f, a = 0.f;
#pragma unroll
    for (int s = 0; s < NSPLIT; s++) {
        int p  = bh * NSPLIT + s;
        float e = __expf(g_ml[2 * p] - M);      // 0 for empty splits
        lt += g_ml[2 * p + 1] * e;
        a  += g_acc[(size_t)p * DD + d] * e;
    }

    const int idx = bh * DD + d;                // b*HIDDEN + h*DD + d
    out[idx] = hidden[idx] + a / lt;
}

// ---------------------------------------------------------------------------
extern "C" void kernel_launch(void* const* d_in, const int* in_sizes, int n_in,
                              void* d_out, int out_size) {
    const float* hidden = (const float*)d_in[0];   // [B, HIDDEN]
    const float* kc     = (const float*)d_in[1];   // [NB, BS, H, D]
    const float* vc     = (const float*)d_in[2];   // [NB, BS, H, D]
    const int*   bt     = (const int*)  d_in[3];   // [B, MB]
    const int*   cl     = (const int*)  d_in[4];   // [B]
    const float* w      = (const float*)d_in[5];   // [HIDDEN]
    float* out = (float*)d_out;

    rms_kernel<<<BB, 256>>>(hidden, w);

    dim3 grid(NSPLIT, HH, BB);
    attn_partial<<<grid, 256>>>(kc, vc, bt, cl);

    attn_reduce<<<BB * HH, DD>>>(hidden, out);
}

// round 15
// speedup vs baseline: 1.0033x; 1.0030x over previous
#include <cuda_runtime.h>

// Problem constants (fixed by the reference)
#define BB      16      // batch
#define HH      32      // heads
#define DD      128     // head dim
#define NBLK    1024    // cache blocks
#define BSZ     16      // tokens per block
#define MBLK    128     // max blocks per seq
#define SEQ     (MBLK * BSZ)   // 2048
#define HIDDEN  (HH * DD)      // 4096

#define NSPLIT  8
#define CHUNK   (SEQ / NSPLIT)     // 256 tokens per split
#define NWARP   8
#define TPW     (CHUNK / NWARP)    // 32 tokens per warp

// Scratch (device globals — no allocation allowed)
__device__ float g_q[BB * HIDDEN];                    // normalized q
__device__ float g_acc[BB * HH * NSPLIT * DD];        // split partial accumulators
__device__ float g_ml[BB * HH * NSPLIT * 2];          // split (max, sumexp)

// ---------------------------------------------------------------------------
// Kernel 1: RMSNorm -> q scratch.  One CTA per batch row (4096 f32).
// ---------------------------------------------------------------------------
__global__ void rms_kernel(const float* __restrict__ x,
                           const float* __restrict__ w) {
    const int b = blockIdx.x;
    const float4* row = (const float4*)(x + b * HIDDEN);   // 1024 float4
    const int tid  = threadIdx.x;                           // 256 threads
    const int lane = tid & 31;
    const int warp = tid >> 5;

    float4 vals[4];
    float ss = 0.f;
#pragma unroll
    for (int i = 0; i < 4; i++) {
        float4 v = row[tid + i * 256];
        vals[i] = v;
        ss += v.x * v.x + v.y * v.y + v.z * v.z + v.w * v.w;
    }
#pragma unroll
    for (int o = 16; o; o >>= 1) ss += __shfl_xor_sync(0xffffffffu, ss, o);

    __shared__ float sred[8];
    __shared__ float s_inv;
    if (lane == 0) sred[warp] = ss;
    __syncthreads();
    if (tid == 0) {
        float t = 0.f;
#pragma unroll
        for (int i = 0; i < 8; i++) t += sred[i];
        s_inv = rsqrtf(t * (1.0f / HIDDEN) + 1e-6f);
    }
    __syncthreads();
    const float inv = s_inv;

    const float4* w4 = (const float4*)w;
    float4* q4 = (float4*)(g_q + b * HIDDEN);
#pragma unroll
    for (int i = 0; i < 4; i++) {
        int idx = tid + i * 256;
        float4 v = vals[i];
        float4 ww = w4[idx];
        float4 o;
        o.x = v.x * inv * ww.x;
        o.y = v.y * inv * ww.y;
        o.z = v.z * inv * ww.z;
        o.w = v.w * inv * ww.w;
        q4[idx] = o;
    }
}

// ---------------------------------------------------------------------------
// Kernel 2: split paged attention (flash-decode partial).
// grid = (NSPLIT, H, B), block = 256 (8 warps). Warp-per-token dot products.
// ---------------------------------------------------------------------------
__global__ void __launch_bounds__(256, 8)
attn_partial(const float* __restrict__ kc,
             const float* __restrict__ vc,
             const int*   __restrict__ bt,
             const int*   __restrict__ cl) {
    const int split = blockIdx.x;
    const int h     = blockIdx.y;
    const int b     = blockIdx.z;

    const int L     = cl[b];
    const int start = split * CHUNK;
    const int pidx  = (b * HH + h) * NSPLIT + split;

    if (start >= L) {
        if (threadIdx.x == 0) {
            g_ml[2 * pidx]     = -1e30f;
            g_ml[2 * pidx + 1] = 0.f;
        }
        return;
    }
    const int end = min(start + CHUNK, L);

    __shared__ int   bt_s[CHUNK / BSZ];          // 16 block ids for this chunk
    __shared__ float s_m[NWARP], s_l[NWARP];
    __shared__ float s_acc[NWARP][DD];

    if (threadIdx.x < CHUNK / BSZ)
        bt_s[threadIdx.x] = bt[b * MBLK + (start >> 4) + threadIdx.x];

    const int warp = threadIdx.x >> 5;
    const int lane = threadIdx.x & 31;

    const float4 q4 = ((const float4*)(g_q + b * HIDDEN + h * DD))[lane];
    __syncthreads();

    const float scale = 0.08838834764831845f;   // 1/sqrt(128)

    float  m = -1e30f, l = 0.f;
    float4 acc = make_float4(0.f, 0.f, 0.f, 0.f);

    const int t0 = start + warp * TPW;
    const int t1 = min(t0 + TPW, end);

    int t = t0;
    // 2-token unrolled main loop: issue both K/V pairs before updating state.
    for (; t + 1 < t1; t += 2) {
        int lc0 = t - start, lc1 = lc0 + 1;
        size_t r0 = ((size_t)bt_s[lc0 >> 4] * BSZ + (t & (BSZ - 1))) * HH + h;
        size_t r1 = ((size_t)bt_s[lc1 >> 4] * BSZ + ((t + 1) & (BSZ - 1))) * HH + h;
        float4 k0 = __ldg((const float4*)(kc + r0 * DD) + lane);
        float4 k1 = __ldg((const float4*)(kc + r1 * DD) + lane);
        float4 v0 = __ldg((const float4*)(vc + r0 * DD) + lane);
        float4 v1 = __ldg((const float4*)(vc + r1 * DD) + lane);

        float s0 = k0.x * q4.x + k0.y * q4.y + k0.z * q4.z + k0.w * q4.w;
        float s1 = k1.x * q4.x + k1.y * q4.y + k1.z * q4.z + k1.w * q4.w;
#pragma unroll
        for (int o = 16; o; o >>= 1) {
            s0 += __shfl_xor_sync(0xffffffffu, s0, o);
            s1 += __shfl_xor_sync(0xffffffffu, s1, o);
        }
        s0 *= scale;
        s1 *= scale;

        float mn    = fmaxf(m, fmaxf(s0, s1));
        float alpha = __expf(m - mn);
        float p0    = __expf(s0 - mn);
        float p1    = __expf(s1 - mn);
        l = l * alpha + p0 + p1;
        acc.x = acc.x * alpha + p0 * v0.x + p1 * v1.x;
        acc.y = acc.y * alpha + p0 * v0.y + p1 * v1.y;
        acc.z = acc.z * alpha + p0 * v0.z + p1 * v1.z;
        acc.w = acc.w * alpha + p0 * v0.w + p1 * v1.w;
        m = mn;
    }
    // tail (0 or 1 token)
    for (; t < t1; ++t) {
        int lc = t - start;
        size_t r = ((size_t)bt_s[lc >> 4] * BSZ + (t & (BSZ - 1))) * HH + h;
        float4 k = __ldg((const float4*)(kc + r * DD) + lane);
        float4 v = __ldg((const float4*)(vc + r * DD) + lane);
        float s = k.x * q4.x + k.y * q4.y + k.z * q4.z + k.w * q4.w;
#pragma unroll
        for (int o = 16; o; o >>= 1) s += __shfl_xor_sync(0xffffffffu, s, o);
        s *= scale;
        float mn    = fmaxf(m, s);
        float alpha = __expf(m - mn);
        float p     = __expf(s - mn);
        l = l * alpha + p;
        acc.x = acc.x * alpha + p * v.x;
        acc.y = acc.y * alpha + p * v.y;
        acc.z = acc.z * alpha + p * v.z;
        acc.w = acc.w * alpha + p * v.w;
        m = mn;
    }

    // Combine the 8 warp partials.
    ((float4*)s_acc[warp])[lane] = acc;
    if (lane == 0) { s_m[warp] = m; s_l[warp] = l; }
    __syncthreads();

    if (threadIdx.x < DD) {
        const int d = threadIdx.x;
        float M = -1e30f;
#pragma unroll
        for (int w = 0; w < NWARP; w++) M = fmaxf(M, s_m[w]);
        float lt = 0.f, a = 0.f;
#pragma unroll
        for (int w = 0; w < NWARP; w++) {
            float e = __expf(s_m[w] - M);
            lt += s_l[w] * e;
            a  += s_acc[w][d] * e;
        }
        g_acc[(size_t)pidx * DD + d] = a;
        if (d == 0) {
            g_ml[2 * pidx]     = M;
            g_ml[2 * pidx + 1] = lt;
        }
    }
}

// ---------------------------------------------------------------------------
// Kernel 3: reduce splits + residual add. grid = B*H, block = 128.
// ---------------------------------------------------------------------------
__global__ void attn_reduce(const float* __restrict__ hidden,
                            float* __restrict__ out) {
    const int bh = blockIdx.x;           // b*H + h
    const int d  = threadIdx.x;          // 0..127

    float M = -1e30f;
#pragma unroll
    for (int s = 0; s < NSPLIT; s++)
        M = fmaxf(M, g_ml[2 * (bh * NSPLIT + s)]);

    float lt = 0.f, a = 0.f;
#pragma unroll
    for (int s = 0; s < NSPLIT; s++) {
        int p  = bh * NSPLIT + s;
        float e = __expf(g_ml[2 * p] - M);      // 0 for empty splits
        lt += g_ml[2 * p + 1] * e;
        a  += g_acc[(size_t)p * DD + d] * e;
    }

    const int idx = bh * DD + d;                // b*HIDDEN + h*DD + d
    out[idx] = hidden[idx] + a / lt;
}

// ---------------------------------------------------------------------------
extern "C" void kernel_launch(void* const* d_in, const int* in_sizes, int n_in,
                              void* d_out, int out_size) {
    const float* hidden = (const float*)d_in[0];   // [B, HIDDEN]
    const float* kc     = (const float*)d_in[1];   // [NB, BS, H, D]
    const float* vc     = (const float*)d_in[2];   // [NB, BS, H, D]
    const int*   bt     = (const int*)  d_in[3];   // [B, MB]
    const int*   cl     = (const int*)  d_in[4];   // [B]
    const float* w      = (const float*)d_in[5];   // [HIDDEN]
    float* out = (float*)d_out;

    rms_kernel<<<BB, 256>>>(hidden, w);

    dim3 grid(NSPLIT, HH, BB);
    attn_partial<<<grid, 256>>>(kc, vc, bt, cl);

    attn_reduce<<<BB * HH, DD>>>(hidden, out);
}

// round 16
// speedup vs baseline: 1.0067x; 1.0033x over previous
#include <cuda_runtime.h>

// Problem constants (fixed by the reference)
#define BB      16      // batch
#define HH      32      // heads
#define DD      128     // head dim
#define NBLK    1024    // cache blocks
#define BSZ     16      // tokens per block
#define MBLK    128     // max blocks per seq
#define SEQ     (MBLK * BSZ)   // 2048
#define HIDDEN  (HH * DD)      // 4096

#define NSPLIT  8
#define CHUNK   (SEQ / NSPLIT)     // 256 tokens per split
#define NWARP   8
#define TPW     (CHUNK / NWARP)    // 32 tokens per warp

// Scratch (device globals — no allocation allowed)
__device__ float g_q[BB * HIDDEN];                    // normalized q
__device__ float g_acc[BB * HH * NSPLIT * DD];        // split partial accumulators
__device__ float g_ml[BB * HH * NSPLIT * 2];          // split (max, sumexp)

// ---------------------------------------------------------------------------
// Kernel 1: RMSNorm -> q scratch.  One CTA per batch row (4096 f32).
// ---------------------------------------------------------------------------
__global__ void rms_kernel(const float* __restrict__ x,
                           const float* __restrict__ w) {
    const int b = blockIdx.x;
    const float4* row = (const float4*)(x + b * HIDDEN);   // 1024 float4
    const int tid  = threadIdx.x;                           // 256 threads
    const int lane = tid & 31;
    const int warp = tid >> 5;

    float4 vals[4];
    float ss = 0.f;
#pragma unroll
    for (int i = 0; i < 4; i++) {
        float4 v = row[tid + i * 256];
        vals[i] = v;
        ss += v.x * v.x + v.y * v.y + v.z * v.z + v.w * v.w;
    }
#pragma unroll
    for (int o = 16; o; o >>= 1) ss += __shfl_xor_sync(0xffffffffu, ss, o);

    __shared__ float sred[8];
    __shared__ float s_inv;
    if (lane == 0) sred[warp] = ss;
    __syncthreads();
    if (tid == 0) {
        float t = 0.f;
#pragma unroll
        for (int i = 0; i < 8; i++) t += sred[i];
        s_inv = rsqrtf(t * (1.0f / HIDDEN) + 1e-6f);
    }
    __syncthreads();
    const float inv = s_inv;

    const float4* w4 = (const float4*)w;
    float4* q4 = (float4*)(g_q + b * HIDDEN);
#pragma unroll
    for (int i = 0; i < 4; i++) {
        int idx = tid + i * 256;
        float4 v = vals[i];
        float4 ww = w4[idx];
        float4 o;
        o.x = v.x * inv * ww.x;
        o.y = v.y * inv * ww.y;
        o.z = v.z * inv * ww.z;
        o.w = v.w * inv * ww.w;
        q4[idx] = o;
    }
}

// ---------------------------------------------------------------------------
// Kernel 2: split paged attention (flash-decode partial).
// grid = (NSPLIT, H, B), block = 256 (8 warps). Warp-per-token dot products.
// ---------------------------------------------------------------------------
__global__ void __launch_bounds__(256, 8)
attn_partial(const float* __restrict__ kc,
             const float* __restrict__ vc,
             const int*   __restrict__ bt,
             const int*   __restrict__ cl) {
    const int split = blockIdx.x;
    const int h     = blockIdx.y;
    const int b     = blockIdx.z;

    const int L     = cl[b];
    const int start = split * CHUNK;
    const int pidx  = (b * HH + h) * NSPLIT + split;

    if (start >= L) {
        if (threadIdx.x == 0) {
            g_ml[2 * pidx]     = -1e30f;
            g_ml[2 * pidx + 1] = 0.f;
        }
        return;
    }
    const int end = min(start + CHUNK, L);

    __shared__ int   bt_s[CHUNK / BSZ];          // 16 block ids for this chunk
    __shared__ float s_m[NWARP], s_l[NWARP];
    __shared__ float s_acc[NWARP][DD];

    if (threadIdx.x < CHUNK / BSZ)
        bt_s[threadIdx.x] = bt[b * MBLK + (start >> 4) + threadIdx.x];

    const int warp = threadIdx.x >> 5;
    const int lane = threadIdx.x & 31;

    const float4 q4 = ((const float4*)(g_q + b * HIDDEN + h * DD))[lane];
    __syncthreads();

    const float scale = 0.08838834764831845f;   // 1/sqrt(128)

    float  m = -1e30f, l = 0.f;
    float4 acc = make_float4(0.f, 0.f, 0.f, 0.f);

    const int t0 = start + warp * TPW;
    const int t1 = min(t0 + TPW, end);

    int t = t0;
    // 2-token unrolled main loop: issue both K/V pairs before updating state.
    for (; t + 1 < t1; t += 2) {
        int lc0 = t - start, lc1 = lc0 + 1;
        size_t r0 = ((size_t)bt_s[lc0 >> 4] * BSZ + (t & (BSZ - 1))) * HH + h;
        size_t r1 = ((size_t)bt_s[lc1 >> 4] * BSZ + ((t + 1) & (BSZ - 1))) * HH + h;
        float4 k0 = __ldg((const float4*)(kc + r0 * DD) + lane);
        float4 k1 = __ldg((const float4*)(kc + r1 * DD) + lane);
        float4 v0 = __ldg((const float4*)(vc + r0 * DD) + lane);
        float4 v1 = __ldg((const float4*)(vc + r1 * DD) + lane);

        float s0 = k0.x * q4.x + k0.y * q4.y + k0.z * q4.z + k0.w * q4.w;
        float s1 = k1.x * q4.x + k1.y * q4.y + k1.z * q4.z + k1.w * q4.w;
#pragma unroll
        for (int o = 16; o; o >>= 1) {
            s0 += __shfl_xor_sync(0xffffffffu, s0, o);
            s1 += __shfl_xor_sync(0xffffffffu, s1, o);
        }
        s0 *= scale;
        s1 *= scale;

        float mn    = fmaxf(m, fmaxf(s0, s1));
        float alpha = __expf(m - mn);
        float p0    = __expf(s0 - mn);
        float p1    = __expf(s1 - mn);
        l = l * alpha + p0 + p1;
        acc.x = acc.x * alpha + p0 * v0.x + p1 * v1.x;
        acc.y = acc.y * alpha + p0 * v0.y + p1 * v1.y;
        acc.z = acc.z * alpha + p0 * v0.z + p1 * v1.z;
        acc.w = acc.w * alpha + p0 * v0.w + p1 * v1.w;
        m = mn;
    }
    // tail (0 or 1 token)
    for (; t < t1; ++t) {
        int lc = t - start;
        size_t r = ((size_t)bt_s[lc >> 4] * BSZ + (t & (BSZ - 1))) * HH + h;
        float4 k = __ldg((const float4*)(kc + r * DD) + lane);
        float4 v = __ldg((const float4*)(vc + r * DD) + lane);
        float s = k.x * q4.x + k.y * q4.y + k.z * q4.z + k.w * q4.w;
#pragma unroll
        for (int o = 16; o; o >>= 1) s += __shfl_xor_sync(0xffffffffu, s, o);
        s *= scale;
        float mn    = fmaxf(m, s);
        float alpha = __expf(m - mn);
        float p     = __expf(s - mn);
        l = l * alpha + p;
        acc.x = acc.x * alpha + p * v.x;
        acc.y = acc.y * alpha + p * v.y;
        acc.z = acc.z * alpha + p * v.z;
        acc.w = acc.w * alpha + p * v.w;
        m = mn;
    }

    // Combine the 8 warp partials.
    ((float4*)s_acc[warp])[lane] = acc;
    if (lane == 0) { s_m[warp] = m; s_l[warp] = l; }
    __syncthreads();

    if (threadIdx.x < DD) {
        const int d = threadIdx.x;
        float M = -1e30f;
#pragma unroll
        for (int w = 0; w < NWARP; w++) M = fmaxf(M, s_m[w]);
        float lt = 0.f, a = 0.f;
#pragma unroll
        for (int w = 0; w < NWARP; w++) {
            float e = __expf(s_m[w] - M);
            lt += s_l[w] * e;
            a  += s_acc[w][d] * e;
        }
        g_acc[(size_t)pidx * DD + d] = a;
        if (d == 0) {
            g_ml[2 * pidx]     = M;
            g_ml[2 * pidx + 1] = lt;
        }
    }
}

// ---------------------------------------------------------------------------
// Kernel 3: reduce splits + residual add. grid = B*H, block = 128.
// ---------------------------------------------------------------------------
__global__ void attn_reduce(const float* __restrict__ hidden,
                            float* __restrict__ out) {
    const int bh = blockIdx.x;           // b*H + h
    const int d  = threadIdx.x;          // 0..127

    float M = -1e30f;
#pragma unroll
    for (int s = 0; s < NSPLIT; s++)
        M = fmaxf(M, g_ml[2 * (bh * NSPLIT + s)]);

    float lt = 0.f, a = 0.f;
#pragma unroll
    for (int s = 0; s < NSPLIT; s++) {
        int p  = bh * NSPLIT + s;
        float e = __expf(g_ml[2 * p] - M);      // 0 for empty splits
        lt += g_ml[2 * p + 1] * e;
        a  += g_acc[(size_t)p * DD + d] * e;
    }

    const int idx = bh * DD + d;                // b*HIDDEN + h*DD + d
    out[idx] = hidden[idx] + a / lt;
}

// ---------------------------------------------------------------------------
extern "C" void kernel_launch(void* const* d_in, const int* in_sizes, int n_in,
                              void* d_out, int out_size) {
    const float* hidden = (const float*)d_in[0];   // [B, HIDDEN]
    const float* kc     = (const float*)d_in[1];   // [NB, BS, H, D]
    const float* vc     = (const float*)d_in[2];   // [NB, BS, H, D]
    const int*   bt     = (const int*)  d_in[3];   // [B, MB]
    const int*   cl     = (const int*)  d_in[4];   // [B]
    const float* w      = (const float*)d_in[5];   // [HIDDEN]
    float* out = (float*)d_out;

    rms_kernel<<<BB, 256>>>(hidden, w);

    dim3 grid(NSPLIT, HH, BB);
    attn_partial<<<grid, 256>>>(kc, vc, bt, cl);

    attn_reduce<<<BB * HH, DD>>>(hidden, out);
}